// round 1
// baseline (speedup 1.0000x reference)
#include <cuda_runtime.h>

#define NB 8
#define NS 1024
#define NE 768
#define NH 12
#define ND 64
#define NT (NB*NS)   // 8192 tokens

// Scratch (device globals: allocation-free rule)
__device__ float g_q[NB*NH*NS*ND];     // [B,H,S,D]
__device__ float g_k[NB*NH*NS*ND];
__device__ float g_v[NB*NH*NS*ND];
__device__ float g_attn[NT*NE];        // [B,S,E] concat layout

// ---------------------------------------------------------------------------
// Kernel 1: fused QKV projection. C = X @ W + b, written in [B,H,S,D] layout.
// grid = (T/64, E/64, 3), 256 threads, 64x64x16 tiles, 4x4 microtile.
// ---------------------------------------------------------------------------
__global__ __launch_bounds__(256) void qkv_gemm_kernel(
    const float* __restrict__ X,
    const float* __restrict__ Wq, const float* __restrict__ bq,
    const float* __restrict__ Wk, const float* __restrict__ bk,
    const float* __restrict__ Wv, const float* __restrict__ bv)
{
    const int m0 = blockIdx.x * 64;
    const int n0 = blockIdx.y * 64;
    const int which = blockIdx.z;
    const float* W    = (which == 0) ? Wq : (which == 1) ? Wk : Wv;
    const float* bias = (which == 0) ? bq : (which == 1) ? bk : bv;
    float* dst        = (which == 0) ? g_q : (which == 1) ? g_k : g_v;

    __shared__ float As[16][68];   // A transposed: As[k][m], pad to 68 floats
    __shared__ float Bs[16][64];   // Bs[k][n]

    const int tid = threadIdx.x;
    const int tx = tid & 15;
    const int ty = tid >> 4;

    float acc[4][4] = {};

    for (int k0 = 0; k0 < NE; k0 += 16) {
        {
            const int r  = tid >> 2;         // 0..63
            const int c4 = tid & 3;          // 0..3  (k chunk)
            float4 xv = *(const float4*)(X + (m0 + r) * NE + k0 + c4 * 4);
            As[c4*4+0][r] = xv.x;
            As[c4*4+1][r] = xv.y;
            As[c4*4+2][r] = xv.z;
            As[c4*4+3][r] = xv.w;
            const int kk = tid >> 4;         // 0..15
            const int n4 = tid & 15;         // 0..15
            *(float4*)(&Bs[kk][n4*4]) = *(const float4*)(W + (k0 + kk) * NE + n0 + n4*4);
        }
        __syncthreads();
        #pragma unroll
        for (int kk = 0; kk < 16; kk++) {
            float4 a = *(const float4*)(&As[kk][ty*4]);
            float4 b = *(const float4*)(&Bs[kk][tx*4]);
            float av[4] = {a.x, a.y, a.z, a.w};
            float bw[4] = {b.x, b.y, b.z, b.w};
            #pragma unroll
            for (int i = 0; i < 4; i++)
                #pragma unroll
                for (int j = 0; j < 4; j++)
                    acc[i][j] = fmaf(av[i], bw[j], acc[i][j]);
        }
        __syncthreads();
    }

    const int h = n0 >> 6;                 // BN=64 == D -> whole tile in one head
    float4 bv4 = *(const float4*)(bias + n0 + tx*4);
    #pragma unroll
    for (int i = 0; i < 4; i++) {
        const int t  = m0 + ty*4 + i;
        const int bb = t >> 10;
        const int ss = t & 1023;
        float4 o;
        o.x = acc[i][0] + bv4.x;
        o.y = acc[i][1] + bv4.y;
        o.z = acc[i][2] + bv4.z;
        o.w = acc[i][3] + bv4.w;
        *(float4*)(dst + ((bb*NH + h)*NS + ss)*ND + tx*4) = o;
    }
}

// ---------------------------------------------------------------------------
// Kernel 2: flash attention (fp32, online softmax).
// grid = (S/64, B*H), 256 threads. 64-row Q tile, 64-row KV tiles.
// smem tiles stride-padded to 68 floats. Row stats live in registers,
// reduced across the 16 lanes of each tx-group via shfl (width 16).
// S-tile columns mapped j = tx + 16*jj so column-of-rows LDS is <=2-way.
// ---------------------------------------------------------------------------
__global__ __launch_bounds__(256) void flash_attn_kernel()
{
    extern __shared__ float sm[];
    float* Qs = sm;                  // [64][68]
    float* Ks = sm + 64*68;          // [64][68]
    float* Vs = sm + 2*64*68;        // [64][68]
    float* Ps = sm + 3*64*68;        // [64][68]

    const int qt = blockIdx.x;       // q tile 0..15
    const int bh = blockIdx.y;       // 0..95
    const float* Qg = g_q + bh*NS*ND + qt*64*ND;
    const float* Kg = g_k + bh*NS*ND;
    const float* Vg = g_v + bh*NS*ND;

    const int tid = threadIdx.x;
    const int tx = tid & 15;
    const int ty = tid >> 4;

    #pragma unroll
    for (int rep = 0; rep < 4; rep++) {
        int idx = tid + rep*256;
        int r = idx >> 4, c = idx & 15;
        *(float4*)(Qs + r*68 + c*4) = *(const float4*)(Qg + r*64 + c*4);
    }

    float m_i[4], l_i[4], o_acc[4][4];
    #pragma unroll
    for (int i = 0; i < 4; i++) {
        m_i[i] = -3.0e38f;
        l_i[i] = 0.0f;
        #pragma unroll
        for (int j = 0; j < 4; j++) o_acc[i][j] = 0.0f;
    }

    for (int kt = 0; kt < 16; kt++) {
        const float* kg = Kg + kt*64*ND;
        const float* vg = Vg + kt*64*ND;
        #pragma unroll
        for (int rep = 0; rep < 4; rep++) {
            int idx = tid + rep*256;
            int r = idx >> 4, c = idx & 15;
            *(float4*)(Ks + r*68 + c*4) = *(const float4*)(kg + r*64 + c*4);
            *(float4*)(Vs + r*68 + c*4) = *(const float4*)(vg + r*64 + c*4);
        }
        __syncthreads();

        // S = Q @ K^T  (rows i = ty*4+i, cols j = tx + 16*jj)
        float s_acc[4][4] = {};
        #pragma unroll
        for (int d4 = 0; d4 < 16; d4++) {
            float4 a[4], b[4];
            #pragma unroll
            for (int i = 0; i < 4; i++)
                a[i] = *(const float4*)(Qs + (ty*4+i)*68 + d4*4);
            #pragma unroll
            for (int jj = 0; jj < 4; jj++)
                b[jj] = *(const float4*)(Ks + (tx + jj*16)*68 + d4*4);
            #pragma unroll
            for (int i = 0; i < 4; i++)
                #pragma unroll
                for (int jj = 0; jj < 4; jj++)
                    s_acc[i][jj] += a[i].x*b[jj].x + a[i].y*b[jj].y
                                  + a[i].z*b[jj].z + a[i].w*b[jj].w;
        }

        // online softmax per row
        #pragma unroll
        for (int i = 0; i < 4; i++) {
            float sv[4];
            float tm = -3.0e38f;
            #pragma unroll
            for (int jj = 0; jj < 4; jj++) {
                sv[jj] = s_acc[i][jj] * 0.125f;   // 1/sqrt(64)
                tm = fmaxf(tm, sv[jj]);
            }
            #pragma unroll
            for (int off = 1; off < 16; off <<= 1)
                tm = fmaxf(tm, __shfl_xor_sync(0xffffffffu, tm, off, 16));
            const float mn = fmaxf(m_i[i], tm);
            const float al = __expf(m_i[i] - mn);
            float rs = 0.0f;
            #pragma unroll
            for (int jj = 0; jj < 4; jj++) {
                float p = __expf(sv[jj] - mn);
                Ps[(ty*4+i)*68 + tx + jj*16] = p;
                rs += p;
            }
            #pragma unroll
            for (int off = 1; off < 16; off <<= 1)
                rs += __shfl_xor_sync(0xffffffffu, rs, off, 16);
            l_i[i] = l_i[i]*al + rs;
            m_i[i] = mn;
            #pragma unroll
            for (int j = 0; j < 4; j++) o_acc[i][j] *= al;
        }
        __syncthreads();

        // O += P @ V  (cols d = tx*4 + j)
        #pragma unroll
        for (int j4 = 0; j4 < 16; j4++) {
            float4 pa[4], vb[4];
            #pragma unroll
            for (int i = 0; i < 4; i++)
                pa[i] = *(const float4*)(Ps + (ty*4+i)*68 + j4*4);
            #pragma unroll
            for (int jj = 0; jj < 4; jj++)
                vb[jj] = *(const float4*)(Vs + (j4*4+jj)*68 + tx*4);
            #pragma unroll
            for (int i = 0; i < 4; i++) {
                float pv[4] = {pa[i].x, pa[i].y, pa[i].z, pa[i].w};
                #pragma unroll
                for (int jj = 0; jj < 4; jj++) {
                    o_acc[i][0] = fmaf(pv[jj], vb[jj].x, o_acc[i][0]);
                    o_acc[i][1] = fmaf(pv[jj], vb[jj].y, o_acc[i][1]);
                    o_acc[i][2] = fmaf(pv[jj], vb[jj].z, o_acc[i][2]);
                    o_acc[i][3] = fmaf(pv[jj], vb[jj].w, o_acc[i][3]);
                }
            }
        }
        __syncthreads();
    }

    const int bb = bh / NH;
    const int h  = bh % NH;
    #pragma unroll
    for (int i = 0; i < 4; i++) {
        const int ss = qt*64 + ty*4 + i;
        const float inv = 1.0f / l_i[i];
        float4 o;
        o.x = o_acc[i][0]*inv;
        o.y = o_acc[i][1]*inv;
        o.z = o_acc[i][2]*inv;
        o.w = o_acc[i][3]*inv;
        *(float4*)(g_attn + (bb*NS + ss)*NE + h*ND + tx*4) = o;
    }
}

// ---------------------------------------------------------------------------
// Kernel 3: output projection. out = attn_concat @ Wo + bo
// ---------------------------------------------------------------------------
__global__ __launch_bounds__(256) void out_gemm_kernel(
    const float* __restrict__ Wo, const float* __restrict__ bo,
    float* __restrict__ out)
{
    const int m0 = blockIdx.x * 64;
    const int n0 = blockIdx.y * 64;

    __shared__ float As[16][68];
    __shared__ float Bs[16][64];

    const int tid = threadIdx.x;
    const int tx = tid & 15;
    const int ty = tid >> 4;

    float acc[4][4] = {};

    for (int k0 = 0; k0 < NE; k0 += 16) {
        {
            const int r  = tid >> 2;
            const int c4 = tid & 3;
            float4 xv = *(const float4*)(g_attn + (m0 + r) * NE + k0 + c4 * 4);
            As[c4*4+0][r] = xv.x;
            As[c4*4+1][r] = xv.y;
            As[c4*4+2][r] = xv.z;
            As[c4*4+3][r] = xv.w;
            const int kk = tid >> 4;
            const int n4 = tid & 15;
            *(float4*)(&Bs[kk][n4*4]) = *(const float4*)(Wo + (k0 + kk) * NE + n0 + n4*4);
        }
        __syncthreads();
        #pragma unroll
        for (int kk = 0; kk < 16; kk++) {
            float4 a = *(const float4*)(&As[kk][ty*4]);
            float4 b = *(const float4*)(&Bs[kk][tx*4]);
            float av[4] = {a.x, a.y, a.z, a.w};
            float bw[4] = {b.x, b.y, b.z, b.w};
            #pragma unroll
            for (int i = 0; i < 4; i++)
                #pragma unroll
                for (int j = 0; j < 4; j++)
                    acc[i][j] = fmaf(av[i], bw[j], acc[i][j]);
        }
        __syncthreads();
    }

    float4 bv4 = *(const float4*)(bo + n0 + tx*4);
    #pragma unroll
    for (int i = 0; i < 4; i++) {
        const int t = m0 + ty*4 + i;
        float4 o;
        o.x = acc[i][0] + bv4.x;
        o.y = acc[i][1] + bv4.y;
        o.z = acc[i][2] + bv4.z;
        o.w = acc[i][3] + bv4.w;
        *(float4*)(out + t*NE + n0 + tx*4) = o;
    }
}

// ---------------------------------------------------------------------------
extern "C" void kernel_launch(void* const* d_in, const int* in_sizes, int n_in,
                              void* d_out, int out_size)
{
    const float* X  = (const float*)d_in[0];
    const float* Wq = (const float*)d_in[1];
    const float* bq = (const float*)d_in[2];
    const float* Wk = (const float*)d_in[3];
    const float* bk = (const float*)d_in[4];
    const float* Wv = (const float*)d_in[5];
    const float* bv = (const float*)d_in[6];
    const float* Wo = (const float*)d_in[7];
    const float* bo = (const float*)d_in[8];
    float* out = (float*)d_out;

    const int flash_smem = 4 * 64 * 68 * (int)sizeof(float);   // 69632 B
    cudaFuncSetAttribute(flash_attn_kernel,
                         cudaFuncAttributeMaxDynamicSharedMemorySize, flash_smem);

    dim3 g1(NT/64, NE/64, 3);
    qkv_gemm_kernel<<<g1, 256>>>(X, Wq, bq, Wk, bk, Wv, bv);

    dim3 g2(NS/64, NB*NH);
    flash_attn_kernel<<<g2, 256, flash_smem>>>();

    dim3 g3(NT/64, NE/64);
    out_gemm_kernel<<<g3, 256>>>(Wo, bo, out);
}

// round 3
// speedup vs baseline: 2.4180x; 2.4180x over previous
#include <cuda_runtime.h>
#include <cstdint>

#define NB 8
#define NS 1024
#define NE 768
#define NH 12
#define ND 64
#define NT (NB*NS)   // 8192 tokens

// Scratch (device globals: allocation-free rule)
__device__ float g_q[NB*NH*NS*ND];     // [B,H,S,D]
__device__ float g_k[NB*NH*NS*ND];
__device__ float g_v[NB*NH*NS*ND];
__device__ float g_attn[NT*NE];        // [B,S,E] concat layout

// ---------------------------------------------------------------------------
__device__ __forceinline__ uint32_t f2tf(float f) {
    uint32_t r;
    asm("cvt.rna.tf32.f32 %0, %1;" : "=r"(r) : "f"(f));
    return r;
}
// D += A*B  (m16n8k8 tf32, A row-major, B col-major)
__device__ __forceinline__ void mma_tf32(float* d, const uint32_t* a, const uint32_t* b) {
    asm volatile(
        "mma.sync.aligned.m16n8k8.row.col.f32.tf32.tf32.f32 "
        "{%0,%1,%2,%3}, {%4,%5,%6,%7}, {%8,%9}, {%0,%1,%2,%3};"
        : "+f"(d[0]), "+f"(d[1]), "+f"(d[2]), "+f"(d[3])
        : "r"(a[0]), "r"(a[1]), "r"(a[2]), "r"(a[3]), "r"(b[0]), "r"(b[1]));
}

// ---------------------------------------------------------------------------
// GEMM: D[M x 768] = A[M x 768] @ W[768 x 768] + bias, tf32 mma.sync.
// BM=128, BN=128, BK=16. 256 threads = 8 warps (4m x 2n), warp tile 32x64.
// dst_sel: 0/1/2 -> g_q/g_k/g_v ([B,H,S,D] split-head), 3 -> Dext ([T,E]).
// Aext == null -> read from g_attn.
// ---------------------------------------------------------------------------
#define ASTR 20     // As row stride (floats)
#define BSTR 136    // Bs row stride (floats)

__global__ __launch_bounds__(256) void gemm_tf32_kernel(
    const float* __restrict__ Aext, const float* __restrict__ W,
    const float* __restrict__ bias, float* __restrict__ Dext, int dst_sel)
{
    __shared__ __align__(16) uint32_t As[128 * ASTR];   // As[m][k]
    __shared__ __align__(16) uint32_t Bs[16 * BSTR];    // Bs[k][n]

    const float* A = Aext ? Aext : g_attn;
    float* D = (dst_sel == 0) ? g_q : (dst_sel == 1) ? g_k :
               (dst_sel == 2) ? g_v : Dext;

    const int tid  = threadIdx.x;
    const int wid  = tid >> 5, lane = tid & 31;
    const int gid  = lane >> 2, tig = lane & 3;
    const int wm   = wid >> 1, wn = wid & 1;
    const int m0   = blockIdx.x * 128;
    const int n0   = blockIdx.y * 128;

    float c[2][8][4] = {};

    for (int k0 = 0; k0 < NE; k0 += 16) {
        // stage A tile (128x16), 2 float4 per thread
        #pragma unroll
        for (int i = 0; i < 2; i++) {
            int f = tid + i * 256;
            int r = f >> 2, cc = (f & 3) * 4;
            float4 v = *(const float4*)(A + (size_t)(m0 + r) * NE + k0 + cc);
            uint4 o = { f2tf(v.x), f2tf(v.y), f2tf(v.z), f2tf(v.w) };
            *(uint4*)(&As[r * ASTR + cc]) = o;
        }
        // stage B tile (16x128) straight from W rows, 2 float4 per thread
        #pragma unroll
        for (int i = 0; i < 2; i++) {
            int f = tid + i * 256;
            int r = f >> 5, cc = (f & 31) * 4;
            float4 v = *(const float4*)(W + (size_t)(k0 + r) * NE + n0 + cc);
            uint4 o = { f2tf(v.x), f2tf(v.y), f2tf(v.z), f2tf(v.w) };
            *(uint4*)(&Bs[r * BSTR + cc]) = o;
        }
        __syncthreads();

        #pragma unroll
        for (int kk = 0; kk < 2; kk++) {
            uint32_t a[2][4];
            #pragma unroll
            for (int mi = 0; mi < 2; mi++) {
                int mr = wm * 32 + mi * 16;
                a[mi][0] = As[(mr + gid    ) * ASTR + kk * 8 + tig    ];
                a[mi][1] = As[(mr + gid + 8) * ASTR + kk * 8 + tig    ];
                a[mi][2] = As[(mr + gid    ) * ASTR + kk * 8 + tig + 4];
                a[mi][3] = As[(mr + gid + 8) * ASTR + kk * 8 + tig + 4];
            }
            #pragma unroll
            for (int nt = 0; nt < 8; nt++) {
                uint32_t b[2];
                int nc = wn * 64 + nt * 8 + gid;
                b[0] = Bs[(kk * 8 + tig    ) * BSTR + nc];
                b[1] = Bs[(kk * 8 + tig + 4) * BSTR + nc];
                mma_tf32(c[0][nt], a[0], b);
                mma_tf32(c[1][nt], a[1], b);
            }
        }
        __syncthreads();
    }

    // epilogue
    #pragma unroll
    for (int mi = 0; mi < 2; mi++) {
        const int r0 = m0 + wm * 32 + mi * 16 + gid;
        #pragma unroll
        for (int nt = 0; nt < 8; nt++) {
            const int n = n0 + wn * 64 + nt * 8 + 2 * tig;
            const float bx = bias[n], by = bias[n + 1];
            float2 lo = { c[mi][nt][0] + bx, c[mi][nt][1] + by };
            float2 hi = { c[mi][nt][2] + bx, c[mi][nt][3] + by };
            if (dst_sel < 3) {
                const int h = n >> 6, d = n & 63;
                const int b0_ = r0 >> 10, s0 = r0 & 1023;
                const int b1_ = (r0 + 8) >> 10, s1 = (r0 + 8) & 1023;
                *(float2*)(D + (((size_t)b0_ * NH + h) * NS + s0) * ND + d) = lo;
                *(float2*)(D + (((size_t)b1_ * NH + h) * NS + s1) * ND + d) = hi;
            } else {
                *(float2*)(D + (size_t)r0 * NE + n) = lo;
                *(float2*)(D + (size_t)(r0 + 8) * NE + n) = hi;
            }
        }
    }
}

// ---------------------------------------------------------------------------
// Flash attention on tf32 mma.sync. grid=(16, 96), 128 threads (4 warps).
// Q tile 64 rows (16 per warp, Q frags register-resident), KV tiles 64 rows.
// smem: Ks, Vs fp-tf32 [64][72]; Ps overlays Qs (warp-private rows).
// ---------------------------------------------------------------------------
#define FS 72

__global__ __launch_bounds__(128) void flash_tf32_kernel()
{
    extern __shared__ uint32_t sm[];
    uint32_t* Qs = sm;                 // [64][FS] -> becomes Ps after Q frags
    uint32_t* Ks = sm + 64 * FS;
    uint32_t* Vs = sm + 2 * 64 * FS;
    uint32_t* Ps = Qs;

    const int qt = blockIdx.x;
    const int bh = blockIdx.y;
    const float* Qg = g_q + (size_t)bh * NS * ND + qt * 64 * ND;
    const float* Kg = g_k + (size_t)bh * NS * ND;
    const float* Vg = g_v + (size_t)bh * NS * ND;

    const int tid = threadIdx.x, wid = tid >> 5, lane = tid & 31;
    const int gid = lane >> 2, tig = lane & 3;
    const int mrow = wid * 16;

    // stage Q (pre-scaled by 1/sqrt(D); exact power of 2 -> no extra rounding)
    #pragma unroll
    for (int i = 0; i < 8; i++) {
        int f = tid + i * 128;
        int r = f >> 4, cc = (f & 15) * 4;
        float4 v = *(const float4*)(Qg + r * 64 + cc);
        uint4 o = { f2tf(v.x * 0.125f), f2tf(v.y * 0.125f),
                    f2tf(v.z * 0.125f), f2tf(v.w * 0.125f) };
        *(uint4*)(&Qs[r * FS + cc]) = o;
    }
    __syncthreads();

    // hoist Q fragments (own 16-row slice only)
    uint32_t qf[8][4];
    #pragma unroll
    for (int kk = 0; kk < 8; kk++) {
        qf[kk][0] = Qs[(mrow + gid    ) * FS + kk * 8 + tig    ];
        qf[kk][1] = Qs[(mrow + gid + 8) * FS + kk * 8 + tig    ];
        qf[kk][2] = Qs[(mrow + gid    ) * FS + kk * 8 + tig + 4];
        qf[kk][3] = Qs[(mrow + gid + 8) * FS + kk * 8 + tig + 4];
    }

    float o[8][4] = {};
    float m0r = -1e30f, m1r = -1e30f, l0 = 0.f, l1 = 0.f;

    for (int kt = 0; kt < 16; kt++) {
        __syncthreads();   // previous iter done with Ks/Vs (and Q frags on iter 0)
        #pragma unroll
        for (int i = 0; i < 8; i++) {
            int f = tid + i * 128;
            int r = f >> 4, cc = (f & 15) * 4;
            float4 kv = *(const float4*)(Kg + (size_t)(kt * 64 + r) * 64 + cc);
            uint4 ko = { f2tf(kv.x), f2tf(kv.y), f2tf(kv.z), f2tf(kv.w) };
            *(uint4*)(&Ks[r * FS + cc]) = ko;
            float4 vv = *(const float4*)(Vg + (size_t)(kt * 64 + r) * 64 + cc);
            uint4 vo = { f2tf(vv.x), f2tf(vv.y), f2tf(vv.z), f2tf(vv.w) };
            *(uint4*)(&Vs[r * FS + cc]) = vo;
        }
        __syncthreads();

        // S = Q @ K^T   (s[nt]: rows gid/gid+8, cols nt*8 + 2tig, 2tig+1)
        float s[8][4] = {};
        #pragma unroll
        for (int kk = 0; kk < 8; kk++) {
            #pragma unroll
            for (int nt = 0; nt < 8; nt++) {
                uint32_t b[2];
                b[0] = Ks[(nt * 8 + gid) * FS + kk * 8 + tig    ];
                b[1] = Ks[(nt * 8 + gid) * FS + kk * 8 + tig + 4];
                mma_tf32(s[nt], qf[kk], b);
            }
        }

        // online softmax (rows gid -> s[][0..1], gid+8 -> s[][2..3])
        float mx0 = -1e30f, mx1 = -1e30f;
        #pragma unroll
        for (int nt = 0; nt < 8; nt++) {
            mx0 = fmaxf(mx0, fmaxf(s[nt][0], s[nt][1]));
            mx1 = fmaxf(mx1, fmaxf(s[nt][2], s[nt][3]));
        }
        #pragma unroll
        for (int off = 1; off < 4; off <<= 1) {
            mx0 = fmaxf(mx0, __shfl_xor_sync(0xffffffffu, mx0, off));
            mx1 = fmaxf(mx1, __shfl_xor_sync(0xffffffffu, mx1, off));
        }
        const float mn0 = fmaxf(m0r, mx0), mn1 = fmaxf(m1r, mx1);
        const float al0 = __expf(m0r - mn0), al1 = __expf(m1r - mn1);
        float rs0 = 0.f, rs1 = 0.f;
        #pragma unroll
        for (int nt = 0; nt < 8; nt++) {
            float p0 = __expf(s[nt][0] - mn0);
            float p1 = __expf(s[nt][1] - mn0);
            float p2 = __expf(s[nt][2] - mn1);
            float p3 = __expf(s[nt][3] - mn1);
            rs0 += p0 + p1;  rs1 += p2 + p3;
            const int col = nt * 8 + 2 * tig;
            uint2 w0 = { f2tf(p0), f2tf(p1) };
            uint2 w1 = { f2tf(p2), f2tf(p3) };
            *(uint2*)(&Ps[(mrow + gid    ) * FS + col]) = w0;
            *(uint2*)(&Ps[(mrow + gid + 8) * FS + col]) = w1;
        }
        #pragma unroll
        for (int off = 1; off < 4; off <<= 1) {
            rs0 += __shfl_xor_sync(0xffffffffu, rs0, off);
            rs1 += __shfl_xor_sync(0xffffffffu, rs1, off);
        }
        l0 = l0 * al0 + rs0;  m0r = mn0;
        l1 = l1 * al1 + rs1;  m1r = mn1;
        #pragma unroll
        for (int nt = 0; nt < 8; nt++) {
            o[nt][0] *= al0;  o[nt][1] *= al0;
            o[nt][2] *= al1;  o[nt][3] *= al1;
        }
        __syncwarp();   // P STS -> LDS (warp-private rows)

        // O += P @ V
        #pragma unroll
        for (int kk = 0; kk < 8; kk++) {
            uint32_t a[4];
            a[0] = Ps[(mrow + gid    ) * FS + kk * 8 + tig    ];
            a[1] = Ps[(mrow + gid + 8) * FS + kk * 8 + tig    ];
            a[2] = Ps[(mrow + gid    ) * FS + kk * 8 + tig + 4];
            a[3] = Ps[(mrow + gid + 8) * FS + kk * 8 + tig + 4];
            #pragma unroll
            for (int nt = 0; nt < 8; nt++) {
                uint32_t b[2];
                b[0] = Vs[(kk * 8 + tig    ) * FS + nt * 8 + gid];
                b[1] = Vs[(kk * 8 + tig + 4) * FS + nt * 8 + gid];
                mma_tf32(o[nt], a, b);
            }
        }
    }

    // write O / l  into concat layout [B,S,E]
    const float inv0 = 1.0f / l0, inv1 = 1.0f / l1;
    const int bb = bh / NH, h = bh % NH;
    const int r0 = qt * 64 + mrow + gid;
    const int r1 = r0 + 8;
    #pragma unroll
    for (int nt = 0; nt < 8; nt++) {
        const int col = h * ND + nt * 8 + 2 * tig;
        float2 w0 = { o[nt][0] * inv0, o[nt][1] * inv0 };
        float2 w1 = { o[nt][2] * inv1, o[nt][3] * inv1 };
        *(float2*)(g_attn + ((size_t)bb * NS + r0) * NE + col) = w0;
        *(float2*)(g_attn + ((size_t)bb * NS + r1) * NE + col) = w1;
    }
}

// ---------------------------------------------------------------------------
extern "C" void kernel_launch(void* const* d_in, const int* in_sizes, int n_in,
                              void* d_out, int out_size)
{
    const float* X  = (const float*)d_in[0];
    const float* Wq = (const float*)d_in[1];
    const float* bq = (const float*)d_in[2];
    const float* Wk = (const float*)d_in[3];
    const float* bk = (const float*)d_in[4];
    const float* Wv = (const float*)d_in[5];
    const float* bv = (const float*)d_in[6];
    const float* Wo = (const float*)d_in[7];
    const float* bo = (const float*)d_in[8];
    float* out = (float*)d_out;

    const int flash_smem = 3 * 64 * FS * (int)sizeof(uint32_t);  // 55296 B
    cudaFuncSetAttribute(flash_tf32_kernel,
                         cudaFuncAttributeMaxDynamicSharedMemorySize, flash_smem);

    dim3 gg(NT / 128, NE / 128);   // 64 x 6
    gemm_tf32_kernel<<<gg, 256>>>(X, Wq, bq, nullptr, 0);
    gemm_tf32_kernel<<<gg, 256>>>(X, Wk, bk, nullptr, 1);
    gemm_tf32_kernel<<<gg, 256>>>(X, Wv, bv, nullptr, 2);

    flash_tf32_kernel<<<dim3(NS / 64, NB * NH), 128, flash_smem>>>();

    gemm_tf32_kernel<<<gg, 256>>>(nullptr, Wo, bo, out, 3);
}

// round 4
// speedup vs baseline: 3.2151x; 1.3296x over previous
#include <cuda_runtime.h>
#include <cstdint>

#define NB 8
#define NS 1024
#define NE 768
#define NH 12
#define ND 64
#define NT (NB*NS)   // 8192 tokens

// Scratch (device globals: allocation-free rule)
__device__ float g_q[NB*NH*NS*ND];     // [B,H,S,D]
__device__ float g_k[NB*NH*NS*ND];
__device__ float g_v[NB*NH*NS*ND];
__device__ float g_attn[NT*NE];        // [B,S,E] concat layout

// ---------------------------------------------------------------------------
__device__ __forceinline__ uint32_t f2tf(float f) {
    uint32_t r;
    asm("cvt.rna.tf32.f32 %0, %1;" : "=r"(r) : "f"(f));
    return r;
}
__device__ __forceinline__ void mma_tf32(float* d, const uint32_t* a, const uint32_t* b) {
    asm volatile(
        "mma.sync.aligned.m16n8k8.row.col.f32.tf32.tf32.f32 "
        "{%0,%1,%2,%3}, {%4,%5,%6,%7}, {%8,%9}, {%0,%1,%2,%3};"
        : "+f"(d[0]), "+f"(d[1]), "+f"(d[2]), "+f"(d[3])
        : "r"(a[0]), "r"(a[1]), "r"(a[2]), "r"(a[3]), "r"(b[0]), "r"(b[1]));
}
__device__ __forceinline__ uint32_t smem_u32(const void* p) {
    uint32_t a;
    asm("{ .reg .u64 t; cvta.to.shared.u64 t, %1; cvt.u32.u64 %0, t; }"
        : "=r"(a) : "l"(p));
    return a;
}
__device__ __forceinline__ void cp16(uint32_t dst, const void* src) {
    asm volatile("cp.async.cg.shared.global [%0], [%1], 16;"
                 :: "r"(dst), "l"(src) : "memory");
}
#define CP_COMMIT() asm volatile("cp.async.commit_group;" ::: "memory")
#define CP_WAIT(n)  asm volatile("cp.async.wait_group %0;" :: "n"(n) : "memory")

// ---------------------------------------------------------------------------
// GEMM: D[8192 x 768] = A @ W + bias. BM=128 BN=128 BK=32, double-buffered,
// register-prefetched. 256 threads = 8 warps (4m x 2n), warp tile 32x64.
// mode 0: z picks Wq/Wk/Wv -> g_q/g_k/g_v split-head. mode 1: Wo -> Dext.
// ---------------------------------------------------------------------------
#define GASTR 36
#define GBSTR 136
#define GEMM_SMEM ((2*128*GASTR + 2*32*GBSTR) * 4)   // 71680 B

__global__ __launch_bounds__(256) void gemm_kernel(
    const float* __restrict__ Ain,
    const float* __restrict__ W0, const float* __restrict__ W1,
    const float* __restrict__ W2,
    const float* __restrict__ bq_, const float* __restrict__ bk_,
    const float* __restrict__ bv_,
    float* __restrict__ Dext, int mode)
{
    extern __shared__ uint32_t gsm[];
    uint32_t* As = gsm;                    // [2][128*GASTR]
    uint32_t* Bs = gsm + 2*128*GASTR;      // [2][32*GBSTR]

    const int z = blockIdx.z;
    const float* W    = (mode == 1) ? W0  : (z == 0 ? W0  : z == 1 ? W1  : W2);
    const float* bias = (mode == 1) ? bq_ : (z == 0 ? bq_ : z == 1 ? bk_ : bv_);
    float* D = (mode == 1) ? Dext : (z == 0 ? g_q : z == 1 ? g_k : g_v);
    const float* A = Ain ? Ain : g_attn;

    const int tid = threadIdx.x, wid = tid >> 5, lane = tid & 31;
    const int gid = lane >> 2, tig = lane & 3;
    const int wm = wid >> 1, wn = wid & 1;
    const int m0 = blockIdx.x * 128, n0 = blockIdx.y * 128;

    int ar[4], ac[4], brr[4], bcc[4];
    #pragma unroll
    for (int i = 0; i < 4; i++) {
        int idx = tid + i * 256;
        ar[i] = idx >> 3;  ac[i] = (idx & 7) * 4;     // A: 128 rows x 32
        brr[i] = idx >> 5; bcc[i] = (idx & 31) * 4;   // B: 32 rows x 128
    }

    float4 pa[4], pb[4];
    #pragma unroll
    for (int i = 0; i < 4; i++) {
        pa[i] = *(const float4*)(A + (size_t)(m0 + ar[i]) * NE + ac[i]);
        pb[i] = *(const float4*)(W + (size_t)brr[i] * NE + n0 + bcc[i]);
    }
    #pragma unroll
    for (int i = 0; i < 4; i++) {
        uint4 va = { f2tf(pa[i].x), f2tf(pa[i].y), f2tf(pa[i].z), f2tf(pa[i].w) };
        *(uint4*)(&As[ar[i] * GASTR + ac[i]]) = va;
        uint4 vb = { f2tf(pb[i].x), f2tf(pb[i].y), f2tf(pb[i].z), f2tf(pb[i].w) };
        *(uint4*)(&Bs[brr[i] * GBSTR + bcc[i]]) = vb;
    }

    float c[2][8][4] = {};

    #pragma unroll 1
    for (int kb = 0; kb < 24; kb++) {
        __syncthreads();
        const int cur = kb & 1, nxt = cur ^ 1;
        if (kb < 23) {
            const int k0n = (kb + 1) * 32;
            #pragma unroll
            for (int i = 0; i < 4; i++) {
                pa[i] = *(const float4*)(A + (size_t)(m0 + ar[i]) * NE + k0n + ac[i]);
                pb[i] = *(const float4*)(W + (size_t)(k0n + brr[i]) * NE + n0 + bcc[i]);
            }
        }
        const uint32_t* Ab = As + cur * 128 * GASTR;
        const uint32_t* Bb = Bs + cur * 32 * GBSTR;
        #pragma unroll
        for (int kk = 0; kk < 4; kk++) {
            uint32_t a[2][4];
            #pragma unroll
            for (int mi = 0; mi < 2; mi++) {
                const int mr = wm * 32 + mi * 16;
                a[mi][0] = Ab[(mr + gid    ) * GASTR + kk * 8 + tig    ];
                a[mi][1] = Ab[(mr + gid + 8) * GASTR + kk * 8 + tig    ];
                a[mi][2] = Ab[(mr + gid    ) * GASTR + kk * 8 + tig + 4];
                a[mi][3] = Ab[(mr + gid + 8) * GASTR + kk * 8 + tig + 4];
            }
            #pragma unroll
            for (int nt = 0; nt < 8; nt++) {
                uint32_t b[2];
                const int nc = wn * 64 + nt * 8 + gid;
                b[0] = Bb[(kk * 8 + tig    ) * GBSTR + nc];
                b[1] = Bb[(kk * 8 + tig + 4) * GBSTR + nc];
                mma_tf32(c[0][nt], a[0], b);
                mma_tf32(c[1][nt], a[1], b);
            }
        }
        if (kb < 23) {
            uint32_t* An = As + nxt * 128 * GASTR;
            uint32_t* Bn = Bs + nxt * 32 * GBSTR;
            #pragma unroll
            for (int i = 0; i < 4; i++) {
                uint4 va = { f2tf(pa[i].x), f2tf(pa[i].y), f2tf(pa[i].z), f2tf(pa[i].w) };
                *(uint4*)(&An[ar[i] * GASTR + ac[i]]) = va;
                uint4 vb = { f2tf(pb[i].x), f2tf(pb[i].y), f2tf(pb[i].z), f2tf(pb[i].w) };
                *(uint4*)(&Bn[brr[i] * GBSTR + bcc[i]]) = vb;
            }
        }
    }

    #pragma unroll
    for (int mi = 0; mi < 2; mi++) {
        const int r0 = m0 + wm * 32 + mi * 16 + gid;
        #pragma unroll
        for (int nt = 0; nt < 8; nt++) {
            const int n = n0 + wn * 64 + nt * 8 + 2 * tig;
            const float bx = bias[n], by = bias[n + 1];
            float2 lo = { c[mi][nt][0] + bx, c[mi][nt][1] + by };
            float2 hi = { c[mi][nt][2] + bx, c[mi][nt][3] + by };
            if (mode == 0) {
                const int h = n >> 6, d = n & 63;
                const int b0_ = r0 >> 10, s0 = r0 & 1023;
                const int b1_ = (r0 + 8) >> 10, s1 = (r0 + 8) & 1023;
                *(float2*)(D + (((size_t)b0_ * NH + h) * NS + s0) * ND + d) = lo;
                *(float2*)(D + (((size_t)b1_ * NH + h) * NS + s1) * ND + d) = hi;
            } else {
                *(float2*)(D + (size_t)r0 * NE + n) = lo;
                *(float2*)(D + (size_t)(r0 + 8) * NE + n) = hi;
            }
        }
    }
}

// ---------------------------------------------------------------------------
// Flash attention v2. grid=(8, 96), 128 threads (4 warps). Q tile 128 rows,
// 32 rows/warp (mi=2) -> K/V fragment smem traffic amortized 2x. Q fragments
// register-resident; Q smem region reused for P. cp.async staging:
// K double-buffered, V single-buffered (S-phase hides V latency).
// ---------------------------------------------------------------------------
#define QPS 68
#define KSR 68
#define VSR 72
#define OFF_K  (128*QPS)            // words
#define OFF_V  (OFF_K + 2*64*KSR)
#define FLASH_SMEM ((OFF_V + 64*VSR) * 4)   // 88064 B

__global__ __launch_bounds__(128) void flash_kernel()
{
    extern __shared__ float fsm[];
    float* QP = fsm;
    float* Kb = fsm + OFF_K;
    float* Vb = fsm + OFF_V;
    uint32_t* QPu = (uint32_t*)QP;
    const uint32_t qp_b = smem_u32(QP);
    const uint32_t k_b  = smem_u32(Kb);
    const uint32_t v_b  = smem_u32(Vb);

    const int qt = blockIdx.x, bh = blockIdx.y;
    const float* Qg = g_q + (size_t)bh * NS * ND + qt * 128 * ND;
    const float* Kg = g_k + (size_t)bh * NS * ND;
    const float* Vg = g_v + (size_t)bh * NS * ND;

    const int tid = threadIdx.x, w = tid >> 5, lane = tid & 31;
    const int gid = lane >> 2, tig = lane & 3;

    // stage Q (128x64) + K0 (64x64)
    #pragma unroll
    for (int i = 0; i < 16; i++) {
        int idx = tid + i * 128, r = idx >> 4, c4 = idx & 15;
        cp16(qp_b + (r * QPS + c4 * 4) * 4, Qg + r * 64 + c4 * 4);
    }
    #pragma unroll
    for (int i = 0; i < 8; i++) {
        int idx = tid + i * 128, r = idx >> 4, c4 = idx & 15;
        cp16(k_b + (r * KSR + c4 * 4) * 4, Kg + r * 64 + c4 * 4);
    }
    CP_COMMIT();
    CP_WAIT(0);
    __syncthreads();

    // hoist Q fragments (pre-scaled by 1/8)
    uint32_t qf[2][8][4];
    #pragma unroll
    for (int h = 0; h < 2; h++) {
        const int r = w * 32 + h * 16 + gid;
        #pragma unroll
        for (int kk = 0; kk < 8; kk++) {
            qf[h][kk][0] = f2tf(0.125f * QP[(r    ) * QPS + kk * 8 + tig    ]);
            qf[h][kk][1] = f2tf(0.125f * QP[(r + 8) * QPS + kk * 8 + tig    ]);
            qf[h][kk][2] = f2tf(0.125f * QP[(r    ) * QPS + kk * 8 + tig + 4]);
            qf[h][kk][3] = f2tf(0.125f * QP[(r + 8) * QPS + kk * 8 + tig + 4]);
        }
    }
    __syncthreads();   // all warps done reading Q -> QP becomes P

    // issue V0 (group), K1 (group)
    #pragma unroll
    for (int i = 0; i < 8; i++) {
        int idx = tid + i * 128, r = idx >> 4, c4 = idx & 15;
        cp16(v_b + (r * VSR + c4 * 4) * 4, Vg + r * 64 + c4 * 4);
    }
    CP_COMMIT();
    #pragma unroll
    for (int i = 0; i < 8; i++) {
        int idx = tid + i * 128, r = idx >> 4, c4 = idx & 15;
        cp16(k_b + (64 * KSR + r * KSR + c4 * 4) * 4, Kg + (64 + r) * 64 + c4 * 4);
    }
    CP_COMMIT();

    float o[2][8][4] = {};
    float mrow[2][2], lrow[2][2];
    #pragma unroll
    for (int h = 0; h < 2; h++) { mrow[h][0] = mrow[h][1] = -1e30f; lrow[h][0] = lrow[h][1] = 0.f; }

    #pragma unroll 1
    for (int kt = 0; kt < 16; kt++) {
        const float* Kc = Kb + (kt & 1) * 64 * KSR;

        // S = Q @ K^T, both mi-halves share each B fragment
        float s[2][8][4] = {};
        #pragma unroll
        for (int kk = 0; kk < 8; kk++) {
            #pragma unroll
            for (int nt = 0; nt < 8; nt++) {
                uint32_t b[2];
                b[0] = f2tf(Kc[(nt * 8 + gid) * KSR + kk * 8 + tig    ]);
                b[1] = f2tf(Kc[(nt * 8 + gid) * KSR + kk * 8 + tig + 4]);
                mma_tf32(s[0][nt], qf[0][kk], b);
                mma_tf32(s[1][nt], qf[1][kk], b);
            }
        }

        // online softmax + P store (warp-private rows of QP)
        #pragma unroll
        for (int h = 0; h < 2; h++) {
            const int r = w * 32 + h * 16 + gid;
            float mx0 = -1e30f, mx1 = -1e30f;
            #pragma unroll
            for (int nt = 0; nt < 8; nt++) {
                mx0 = fmaxf(mx0, fmaxf(s[h][nt][0], s[h][nt][1]));
                mx1 = fmaxf(mx1, fmaxf(s[h][nt][2], s[h][nt][3]));
            }
            #pragma unroll
            for (int off = 1; off < 4; off <<= 1) {
                mx0 = fmaxf(mx0, __shfl_xor_sync(0xffffffffu, mx0, off));
                mx1 = fmaxf(mx1, __shfl_xor_sync(0xffffffffu, mx1, off));
            }
            const float mn0 = fmaxf(mrow[h][0], mx0), mn1 = fmaxf(mrow[h][1], mx1);
            const float al0 = __expf(mrow[h][0] - mn0), al1 = __expf(mrow[h][1] - mn1);
            float rs0 = 0.f, rs1 = 0.f;
            #pragma unroll
            for (int nt = 0; nt < 8; nt++) {
                float p0 = __expf(s[h][nt][0] - mn0);
                float p1 = __expf(s[h][nt][1] - mn0);
                float p2 = __expf(s[h][nt][2] - mn1);
                float p3 = __expf(s[h][nt][3] - mn1);
                rs0 += p0 + p1;  rs1 += p2 + p3;
                const int col = nt * 8 + 2 * tig;
                uint2 w0 = { f2tf(p0), f2tf(p1) };
                uint2 w1 = { f2tf(p2), f2tf(p3) };
                *(uint2*)(&QPu[(r    ) * QPS + col]) = w0;
                *(uint2*)(&QPu[(r + 8) * QPS + col]) = w1;
            }
            #pragma unroll
            for (int off = 1; off < 4; off <<= 1) {
                rs0 += __shfl_xor_sync(0xffffffffu, rs0, off);
                rs1 += __shfl_xor_sync(0xffffffffu, rs1, off);
            }
            lrow[h][0] = lrow[h][0] * al0 + rs0;  mrow[h][0] = mn0;
            lrow[h][1] = lrow[h][1] * al1 + rs1;  mrow[h][1] = mn1;
            #pragma unroll
            for (int nt = 0; nt < 8; nt++) {
                o[h][nt][0] *= al0;  o[h][nt][1] *= al0;
                o[h][nt][2] *= al1;  o[h][nt][3] *= al1;
            }
        }

        // wait for V[kt] (K[kt+1] may still be in flight)
        if (kt < 15) { CP_WAIT(1); } else { CP_WAIT(0); }
        __syncthreads();

        // O += P @ V, V fragments cached in regs across both mi-halves
        #pragma unroll
        for (int kk = 0; kk < 8; kk++) {
            uint32_t vb[8][2];
            #pragma unroll
            for (int nt = 0; nt < 8; nt++) {
                vb[nt][0] = f2tf(Vb[(kk * 8 + tig    ) * VSR + nt * 8 + gid]);
                vb[nt][1] = f2tf(Vb[(kk * 8 + tig + 4) * VSR + nt * 8 + gid]);
            }
            #pragma unroll
            for (int h = 0; h < 2; h++) {
                const int r = w * 32 + h * 16 + gid;
                uint32_t a[4];
                a[0] = QPu[(r    ) * QPS + kk * 8 + tig    ];
                a[1] = QPu[(r + 8) * QPS + kk * 8 + tig    ];
                a[2] = QPu[(r    ) * QPS + kk * 8 + tig + 4];
                a[3] = QPu[(r + 8) * QPS + kk * 8 + tig + 4];
                #pragma unroll
                for (int nt = 0; nt < 8; nt++)
                    mma_tf32(o[h][nt], a, vb[nt]);
            }
        }

        if (kt < 15) {
            __syncthreads();   // all warps done with V[kt] and K[kt]
            #pragma unroll
            for (int i = 0; i < 8; i++) {
                int idx = tid + i * 128, r = idx >> 4, c4 = idx & 15;
                cp16(v_b + (r * VSR + c4 * 4) * 4,
                     Vg + (size_t)((kt + 1) * 64 + r) * 64 + c4 * 4);
            }
            CP_COMMIT();
            if (kt < 14) {
                #pragma unroll
                for (int i = 0; i < 8; i++) {
                    int idx = tid + i * 128, r = idx >> 4, c4 = idx & 15;
                    cp16(k_b + ((kt & 1) * 64 * KSR + r * KSR + c4 * 4) * 4,
                         Kg + (size_t)((kt + 2) * 64 + r) * 64 + c4 * 4);
                }
                CP_COMMIT();
                CP_WAIT(2);    // K[kt+1] arrived; V[kt+1], K[kt+2] pending
            } else {
                CP_WAIT(1);    // K[15] arrived; V[15] pending
            }
            __syncthreads();
        }
    }

    // write O (normalized) into concat layout [B,S,E]
    const int bb = bh / NH, hh = bh % NH;
    #pragma unroll
    for (int h = 0; h < 2; h++) {
        const float inv0 = 1.0f / lrow[h][0], inv1 = 1.0f / lrow[h][1];
        const int r0 = qt * 128 + w * 32 + h * 16 + gid;
        const int r1 = r0 + 8;
        #pragma unroll
        for (int nt = 0; nt < 8; nt++) {
            const int col = hh * ND + nt * 8 + 2 * tig;
            float2 w0 = { o[h][nt][0] * inv0, o[h][nt][1] * inv0 };
            float2 w1 = { o[h][nt][2] * inv1, o[h][nt][3] * inv1 };
            *(float2*)(g_attn + ((size_t)bb * NS + r0) * NE + col) = w0;
            *(float2*)(g_attn + ((size_t)bb * NS + r1) * NE + col) = w1;
        }
    }
}

// ---------------------------------------------------------------------------
extern "C" void kernel_launch(void* const* d_in, const int* in_sizes, int n_in,
                              void* d_out, int out_size)
{
    const float* X  = (const float*)d_in[0];
    const float* Wq = (const float*)d_in[1];
    const float* bq = (const float*)d_in[2];
    const float* Wk = (const float*)d_in[3];
    const float* bk = (const float*)d_in[4];
    const float* Wv = (const float*)d_in[5];
    const float* bv = (const float*)d_in[6];
    const float* Wo = (const float*)d_in[7];
    const float* bo = (const float*)d_in[8];
    float* out = (float*)d_out;

    cudaFuncSetAttribute(gemm_kernel,
                         cudaFuncAttributeMaxDynamicSharedMemorySize, GEMM_SMEM);
    cudaFuncSetAttribute(flash_kernel,
                         cudaFuncAttributeMaxDynamicSharedMemorySize, FLASH_SMEM);

    gemm_kernel<<<dim3(NT/128, NE/128, 3), 256, GEMM_SMEM>>>(
        X, Wq, Wk, Wv, bq, bk, bv, nullptr, 0);

    flash_kernel<<<dim3(NS/128, NB*NH), 128, FLASH_SMEM>>>();

    gemm_kernel<<<dim3(NT/128, NE/128, 1), 256, GEMM_SMEM>>>(
        nullptr, Wo, Wo, Wo, bo, bo, bo, out, 1);
}